// round 1
// baseline (speedup 1.0000x reference)
#include <cuda_runtime.h>

#define BATCH 4
#define SEQ   4096
#define DIN   128
#define DOUT  64
#define BQ    64
#define BK    64

// Scratch for Q, K, V projections (12 MB total) — device globals, no allocation.
__device__ float g_q[BATCH * SEQ * DOUT];
__device__ float g_k[BATCH * SEQ * DOUT];
__device__ float g_v[BATCH * SEQ * DOUT];

// ---------------------------------------------------------------------------
// Kernel 1: QKV projection. One block per token row; 192 threads:
//   p = t/64 selects Q/K/V, e = t%64 selects output column.
// Q is pre-scaled by 1/sqrt(DOUT) = 0.125.
// ---------------------------------------------------------------------------
__global__ void qkv_proj_kernel(const float* __restrict__ x,
                                const float* __restrict__ w) {
    __shared__ float xs[DIN];
    const int row = blockIdx.x;          // 0 .. BATCH*SEQ-1
    const int t   = threadIdx.x;         // 0 .. 191
    if (t < DIN) xs[t] = x[row * DIN + t];
    __syncthreads();

    const int p = t >> 6;                // 0,1,2
    const int e = t & 63;
    const float* wp = w + p * DIN * DOUT + e;

    float acc = 0.f;
#pragma unroll 8
    for (int d = 0; d < DIN; d++)
        acc = fmaf(xs[d], wp[d * DOUT], acc);

    if (p == 0) {
        g_q[row * DOUT + e] = acc * 0.125f;   // fold 1/sqrt(64)
    } else if (p == 1) {
        g_k[row * DOUT + e] = acc;
    } else {
        g_v[row * DOUT + e] = acc;
    }
}

// ---------------------------------------------------------------------------
// Kernel 2: flash-attention tile kernel.
//   grid = (SEQ/BQ, BATCH), block = 256 threads as 16x16 (tx, ty).
//   Each thread owns a 4x4 register tile of scores and of the output.
//   Smem: Qs (k-major, 16KB) + KsP (k-major K, reused as row-major P, 16KB)
//         + Vs (natural, 16KB) = exactly 48KB static.
// ---------------------------------------------------------------------------
__global__ __launch_bounds__(256, 2)
void attn_kernel(float* __restrict__ out) {
    __shared__ float Qs[BQ * DOUT];    // Qs[k*64 + qrow]
    __shared__ float KsP[BK * DOUT];   // Ks[k*64 + krow]  -> later P[qrow*64 + kk]
    __shared__ float Vs[BK * DOUT];    // Vs[kk*64 + e]

    const int b   = blockIdx.y;
    const int q0  = blockIdx.x * BQ;
    const int tid = threadIdx.x;
    const int tx  = tid & 15;          // output-column group  (4 cols each)
    const int ty  = tid >> 4;          // q-row group          (4 rows each)

    // Load Q tile transposed (k-major).
    const float* Qg = g_q + (b * SEQ + q0) * DOUT;
    for (int i = tid; i < BQ * DOUT; i += 256) {
        int r = i >> 6, k = i & 63;
        Qs[k * 64 + r] = Qg[i];
    }

    float o[4][4] = {};
    float m[4], l[4];
#pragma unroll
    for (int i = 0; i < 4; i++) { m[i] = -1e30f; l[i] = 0.f; }

    __syncthreads();

    for (int kt = 0; kt < SEQ; kt += BK) {
        const float* Kg = g_k + (b * SEQ + kt) * DOUT;
        const float* Vg = g_v + (b * SEQ + kt) * DOUT;

        // Load K transposed (k-major) and V natural.
        for (int i = tid; i < BK * DOUT; i += 256) {
            int r = i >> 6, k = i & 63;
            KsP[k * 64 + r] = Kg[i];
            Vs[i]           = Vg[i];
        }
        __syncthreads();

        // --- scores: s[i][j] = sum_k Qs[k][ty4+i] * Ks[k][tx4+j] ---
        float s[4][4] = {};
#pragma unroll 4
        for (int k = 0; k < DOUT; k++) {
            const float4 a4 = *(const float4*)&Qs[k * 64 + ty * 4];
            const float4 b4 = *(const float4*)&KsP[k * 64 + tx * 4];
            const float av[4] = {a4.x, a4.y, a4.z, a4.w};
            const float bv[4] = {b4.x, b4.y, b4.z, b4.w};
#pragma unroll
            for (int i = 0; i < 4; i++)
#pragma unroll
                for (int j = 0; j < 4; j++)
                    s[i][j] = fmaf(av[i], bv[j], s[i][j]);
        }

        // --- online softmax update (per q-row; reduce across 16 tx lanes) ---
#pragma unroll
        for (int i = 0; i < 4; i++) {
            float mx = fmaxf(fmaxf(s[i][0], s[i][1]), fmaxf(s[i][2], s[i][3]));
#pragma unroll
            for (int off = 1; off < 16; off <<= 1)
                mx = fmaxf(mx, __shfl_xor_sync(0xffffffffu, mx, off));
            const float mnew = fmaxf(m[i], mx);
            const float corr = __expf(m[i] - mnew);
            float rs = 0.f;
#pragma unroll
            for (int j = 0; j < 4; j++) {
                s[i][j] = __expf(s[i][j] - mnew);
                rs += s[i][j];
            }
#pragma unroll
            for (int off = 1; off < 16; off <<= 1)
                rs += __shfl_xor_sync(0xffffffffu, rs, off);
            l[i] = l[i] * corr + rs;
            m[i] = mnew;
#pragma unroll
            for (int j = 0; j < 4; j++) o[i][j] *= corr;
        }

        __syncthreads();  // all Ks reads done before P overwrites the buffer

        // Write P tile (row-major) into the K buffer.
#pragma unroll
        for (int i = 0; i < 4; i++) {
            float4 p4 = make_float4(s[i][0], s[i][1], s[i][2], s[i][3]);
            *(float4*)&KsP[(ty * 4 + i) * 64 + tx * 4] = p4;
        }
        __syncthreads();

        // --- PV: o[i][j] += sum_kk P[ty4+i][kk] * Vs[kk][tx4+j] ---
#pragma unroll 4
        for (int kk = 0; kk < BK; kk++) {
            const float4 v4 = *(const float4*)&Vs[kk * 64 + tx * 4];
            const float vv[4] = {v4.x, v4.y, v4.z, v4.w};
            float pv[4];
#pragma unroll
            for (int i = 0; i < 4; i++)
                pv[i] = KsP[(ty * 4 + i) * 64 + kk];
#pragma unroll
            for (int i = 0; i < 4; i++)
#pragma unroll
                for (int j = 0; j < 4; j++)
                    o[i][j] = fmaf(pv[i], vv[j], o[i][j]);
        }
        __syncthreads();  // PV reads done before next iter overwrites Ks/Vs
    }

    // Epilogue: normalize and store.
    float* Og = out + (b * SEQ + q0) * DOUT;
#pragma unroll
    for (int i = 0; i < 4; i++) {
        const float rl = __frcp_rn(l[i]);
        float4 r = make_float4(o[i][0] * rl, o[i][1] * rl,
                               o[i][2] * rl, o[i][3] * rl);
        *(float4*)&Og[(ty * 4 + i) * 64 + tx * 4] = r;
    }
}

// ---------------------------------------------------------------------------
extern "C" void kernel_launch(void* const* d_in, const int* in_sizes, int n_in,
                              void* d_out, int out_size) {
    const float* x = (const float*)d_in[0];   // [4,4096,128]
    const float* w = (const float*)d_in[1];   // [3,128,64]
    float* out = (float*)d_out;               // [4,4096,64]

    qkv_proj_kernel<<<BATCH * SEQ, 192>>>(x, w);
    attn_kernel<<<dim3(SEQ / BQ, BATCH), 256>>>(out);
}

// round 2
// speedup vs baseline: 1.2396x; 1.2396x over previous
#include <cuda_runtime.h>

#define BATCH 4
#define SEQ   4096
#define DIN   128
#define DOUT  64
#define BQ    128
#define BK    128
#define KST   132          // padded row stride for k-major Q/K tiles (floats)
#define PST   132          // padded row stride for P tile (floats)

#define QS_OFF 0
#define KS_OFF (QS_OFF + 64 * KST)      // 8448
#define VS_OFF (KS_OFF + 64 * KST)      // 16896
#define PS_OFF (VS_OFF + BK * DOUT)     // 25088
#define CR_OFF (PS_OFF + BQ * PST)      // 41984
#define LR_OFF (CR_OFF + BQ)            // 42112
#define SMEM_FLOATS (LR_OFF + BQ)       // 42240
#define SMEM_BYTES  (SMEM_FLOATS * 4)   // 168960

// Scratch for Q, K, V projections — device globals, no allocation.
__device__ float g_q[BATCH * SEQ * DOUT];
__device__ float g_k[BATCH * SEQ * DOUT];
__device__ float g_v[BATCH * SEQ * DOUT];

typedef unsigned long long u64;

// ---- packed f32x2 helpers (sm_103a dual-rate fp32, PTX-only path) ----------
__device__ __forceinline__ u64 pk2(float lo, float hi) {
    u64 r; asm("mov.b64 %0, {%1, %2};" : "=l"(r) : "f"(lo), "f"(hi)); return r;
}
__device__ __forceinline__ void fma2(u64& d, u64 a, u64 b) {
    asm("fma.rn.f32x2 %0, %1, %2, %0;" : "+l"(d) : "l"(a), "l"(b));
}
__device__ __forceinline__ void mul2(u64& d, u64 a) {
    asm("mul.rn.f32x2 %0, %0, %1;" : "+l"(d) : "l"(a));
}
__device__ __forceinline__ void upk2(u64 v, float& lo, float& hi) {
    asm("mov.b64 {%0, %1}, %2;" : "=f"(lo), "=f"(hi) : "l"(v));
}

// ---------------------------------------------------------------------------
// Kernel 1: QKV projection (unchanged — w is L1-resident; ~58us, not critical).
// ---------------------------------------------------------------------------
__global__ void qkv_proj_kernel(const float* __restrict__ x,
                                const float* __restrict__ w) {
    __shared__ float xs[DIN];
    const int row = blockIdx.x;
    const int t   = threadIdx.x;
    if (t < DIN) xs[t] = x[row * DIN + t];
    __syncthreads();

    const int p = t >> 6;
    const int e = t & 63;
    const float* wp = w + p * DIN * DOUT + e;

    float acc = 0.f;
#pragma unroll 8
    for (int d = 0; d < DIN; d++)
        acc = fmaf(xs[d], wp[d * DOUT], acc);

    if (p == 0)      g_q[row * DOUT + e] = acc * 0.125f;  // fold 1/sqrt(64)
    else if (p == 1) g_k[row * DOUT + e] = acc;
    else             g_v[row * DOUT + e] = acc;
}

// ---------------------------------------------------------------------------
// Kernel 2: flash attention, 128x128 tile, 8x8 thread tile, FFMA2.
//   Score map : tx = tid&15 (8 cols each), ty = tid>>4 (8 rows each)
//   PV map    : tx2 = tid&7 (8 out-cols),  ty2 = tid>>3 (4 rows each)
//   corr/l handed between the two maps via tiny smem arrays.
// ---------------------------------------------------------------------------
__global__ __launch_bounds__(256, 1)
void attn_kernel(float* __restrict__ out) {
    extern __shared__ float sm[];
    float* Qs = sm + QS_OFF;   // [k=64][BQ] padded KST
    float* Ks = sm + KS_OFF;   // [k=64][BK] padded KST
    float* Vs = sm + VS_OFF;   // [BK][DOUT]
    float* Ps = sm + PS_OFF;   // [BQ][BK] padded PST
    float* Cr = sm + CR_OFF;   // corr per q-row
    float* Lr = sm + LR_OFF;   // final l per q-row

    const int b   = blockIdx.y;
    const int q0  = blockIdx.x * BQ;
    const int tid = threadIdx.x;
    const int tx  = tid & 15, ty  = tid >> 4;
    const int tx2 = tid & 7,  ty2 = tid >> 3;

    const float* Qg = g_q + (b * SEQ + q0) * DOUT;
    for (int i = tid; i < BQ * DOUT; i += 256) {
        int r = i >> 6, k = i & 63;
        Qs[k * KST + r] = Qg[i];
    }

    u64 o2[4][4];
#pragma unroll
    for (int i = 0; i < 4; i++)
#pragma unroll
        for (int j = 0; j < 4; j++) o2[i][j] = 0ull;
    float m[8], l[8];
#pragma unroll
    for (int i = 0; i < 8; i++) { m[i] = -1e30f; l[i] = 0.f; }

    __syncthreads();

    for (int kt = 0; kt < SEQ; kt += BK) {
        const float* Kg = g_k + (b * SEQ + kt) * DOUT;
        const float* Vg = g_v + (b * SEQ + kt) * DOUT;
        for (int i = tid; i < BK * DOUT; i += 256) {
            int r = i >> 6, k = i & 63;
            Ks[k * KST + r] = Kg[i];   // padded stride: 4-way max conflict
            Vs[i]           = Vg[i];
        }
        __syncthreads();

        // ---- scores: s[i][j] = sum_k Q[ty8+i][k] * K[tx8+j][k] (FFMA2) ----
        u64 s2[8][4];
#pragma unroll
        for (int i = 0; i < 8; i++)
#pragma unroll
            for (int j = 0; j < 4; j++) s2[i][j] = 0ull;

#pragma unroll 2
        for (int k = 0; k < DOUT; k++) {
            const float4 qa = *(const float4*)&Qs[k * KST + ty * 8];
            const float4 qb = *(const float4*)&Qs[k * KST + ty * 8 + 4];
            const float4 ka = *(const float4*)&Ks[k * KST + tx * 8];
            const float4 kb = *(const float4*)&Ks[k * KST + tx * 8 + 4];
            u64 bp[4] = {pk2(ka.x, ka.y), pk2(ka.z, ka.w),
                         pk2(kb.x, kb.y), pk2(kb.z, kb.w)};
            const float av[8] = {qa.x, qa.y, qa.z, qa.w, qb.x, qb.y, qb.z, qb.w};
#pragma unroll
            for (int i = 0; i < 8; i++) {
                u64 a2 = pk2(av[i], av[i]);
#pragma unroll
                for (int j = 0; j < 4; j++) fma2(s2[i][j], a2, bp[j]);
            }
        }

        // ---- online softmax (score map), write P + corr ----
#pragma unroll
        for (int i = 0; i < 8; i++) {
            float sv[8];
#pragma unroll
            for (int j = 0; j < 4; j++) upk2(s2[i][j], sv[2 * j], sv[2 * j + 1]);
            float mx = sv[0];
#pragma unroll
            for (int j = 1; j < 8; j++) mx = fmaxf(mx, sv[j]);
#pragma unroll
            for (int off = 8; off >= 1; off >>= 1)
                mx = fmaxf(mx, __shfl_xor_sync(0xffffffffu, mx, off));
            const float mnew = fmaxf(m[i], mx);
            const float corr = __expf(m[i] - mnew);
            float rs = 0.f;
#pragma unroll
            for (int j = 0; j < 8; j++) { sv[j] = __expf(sv[j] - mnew); rs += sv[j]; }
#pragma unroll
            for (int off = 8; off >= 1; off >>= 1)
                rs += __shfl_xor_sync(0xffffffffu, rs, off);
            l[i] = l[i] * corr + rs;
            m[i] = mnew;
            const int row = ty * 8 + i;
            if (tx == 0) Cr[row] = corr;
            *(float4*)&Ps[row * PST + tx * 8]     = make_float4(sv[0], sv[1], sv[2], sv[3]);
            *(float4*)&Ps[row * PST + tx * 8 + 4] = make_float4(sv[4], sv[5], sv[6], sv[7]);
        }
        __syncthreads();

        // ---- rescale o, then PV (pv map) ----
#pragma unroll
        for (int i = 0; i < 4; i++) {
            const float c = Cr[ty2 * 4 + i];
            u64 c2 = pk2(c, c);
#pragma unroll
            for (int j = 0; j < 4; j++) mul2(o2[i][j], c2);
        }
#pragma unroll 2
        for (int kk = 0; kk < BK; kk++) {
            const float4 va = *(const float4*)&Vs[kk * DOUT + tx2 * 8];
            const float4 vb = *(const float4*)&Vs[kk * DOUT + tx2 * 8 + 4];
            u64 vp[4] = {pk2(va.x, va.y), pk2(va.z, va.w),
                         pk2(vb.x, vb.y), pk2(vb.z, vb.w)};
#pragma unroll
            for (int i = 0; i < 4; i++) {
                const float p = Ps[(ty2 * 4 + i) * PST + kk];
                u64 p2 = pk2(p, p);
#pragma unroll
                for (int j = 0; j < 4; j++) fma2(o2[i][j], p2, vp[j]);
            }
        }
        __syncthreads();   // protect Ks/Vs/Ps for next tile
    }

    // ---- epilogue: hand l across maps, normalize, store ----
#pragma unroll
    for (int i = 0; i < 8; i++)
        if (tx == 0) Lr[ty * 8 + i] = l[i];
    __syncthreads();

    float* Og = out + (b * SEQ + q0) * DOUT;
#pragma unroll
    for (int i = 0; i < 4; i++) {
        const int row = ty2 * 4 + i;
        const float rl = __frcp_rn(Lr[row]);
        float ov[8];
#pragma unroll
        for (int j = 0; j < 4; j++) upk2(o2[i][j], ov[2 * j], ov[2 * j + 1]);
#pragma unroll
        for (int j = 0; j < 8; j++) ov[j] *= rl;
        *(float4*)&Og[row * DOUT + tx2 * 8]     = make_float4(ov[0], ov[1], ov[2], ov[3]);
        *(float4*)&Og[row * DOUT + tx2 * 8 + 4] = make_float4(ov[4], ov[5], ov[6], ov[7]);
    }
}

// ---------------------------------------------------------------------------
extern "C" void kernel_launch(void* const* d_in, const int* in_sizes, int n_in,
                              void* d_out, int out_size) {
    const float* x = (const float*)d_in[0];   // [4,4096,128]
    const float* w = (const float*)d_in[1];   // [3,128,64]
    float* out = (float*)d_out;               // [4,4096,64]

    cudaFuncSetAttribute(attn_kernel,
                         cudaFuncAttributeMaxDynamicSharedMemorySize, SMEM_BYTES);

    qkv_proj_kernel<<<BATCH * SEQ, 192>>>(x, w);
    attn_kernel<<<dim3(SEQ / BQ, BATCH), 256, SMEM_BYTES>>>(out);
}

// round 4
// speedup vs baseline: 4.3739x; 3.5285x over previous
#include <cuda_runtime.h>
#include <cuda_fp16.h>
#include <cstdint>

#define BATCH 4
#define SEQ   4096
#define DIN   128
#define DOUT  64
#define BQ    128
#define BK    128
#define NTILES (SEQ / BK)

// ---- fp16 scratch (10MB) — device globals, no allocation ----
__device__ __half g_qh[BATCH * SEQ * DOUT];
__device__ __half g_ql[BATCH * SEQ * DOUT];
__device__ __half g_kh[BATCH * SEQ * DOUT];
__device__ __half g_kl[BATCH * SEQ * DOUT];
__device__ __half g_vt[BATCH * DOUT * SEQ];   // transposed: [b][dout][seq]

// ---- smem byte offsets ----
// Q/K tiles: 128 rows x 72 halves (64 data + 8 pad) = 144B/row -> stride 36 b32 (36%32==4, conflict-free)
// Vt/P tiles: rows x 136 halves = 272B/row -> stride 68 b32 (68%32==4)
#define QH_B      0
#define QL_B      18432
#define KH_B(b)   (36864  + (b) * 18432)
#define KL_B(b)   (73728  + (b) * 18432)
#define VT_B(b)   (110592 + (b) * 17408)
#define P_B       145408
#define SMEM_BYTES 180224

__device__ __forceinline__ uint32_t smem_u32(const void* p) {
    uint32_t a;
    asm("{ .reg .u64 t; cvta.to.shared.u64 t, %1; cvt.u32.u64 %0, t; }" : "=r"(a) : "l"(p));
    return a;
}
__device__ __forceinline__ void cp16(uint32_t dst, const void* src) {
    asm volatile("cp.async.cg.shared.global [%0], [%1], 16;" :: "r"(dst), "l"(src));
}
#define CP_COMMIT() asm volatile("cp.async.commit_group;" ::: "memory")
#define CP_WAIT1()  asm volatile("cp.async.wait_group 1;" ::: "memory")

#define MMA16816(c, a0, a1, a2, a3, b0, b1) \
    asm volatile("mma.sync.aligned.m16n8k16.row.col.f32.f16.f16.f32 " \
                 "{%0,%1,%2,%3}, {%4,%5,%6,%7}, {%8,%9}, {%0,%1,%2,%3};" \
                 : "+f"((c)[0]), "+f"((c)[1]), "+f"((c)[2]), "+f"((c)[3]) \
                 : "r"(a0), "r"(a1), "r"(a2), "r"(a3), "r"(b0), "r"(b1))

// ---------------------------------------------------------------------------
// Kernel 1: QKV projection -> fp16 hi/lo splits (Q scaled by 1/8) + V^T.
// ---------------------------------------------------------------------------
__global__ void qkv_proj_kernel(const float* __restrict__ x,
                                const float* __restrict__ w) {
    __shared__ float xs[DIN];
    const int row = blockIdx.x;          // 0 .. BATCH*SEQ-1
    const int t   = threadIdx.x;         // 0 .. 191
    if (t < DIN) xs[t] = x[row * DIN + t];
    __syncthreads();

    const int p = t >> 6;
    const int e = t & 63;
    const float* wp = w + p * DIN * DOUT + e;

    float acc = 0.f;
#pragma unroll 8
    for (int d = 0; d < DIN; d++)
        acc = fmaf(xs[d], wp[d * DOUT], acc);

    if (p == 0) acc *= 0.125f;           // fold 1/sqrt(64)
    const __half hi = __float2half_rn(acc);
    const __half lo = __float2half_rn(acc - __half2float(hi));

    if (p == 0) {
        g_qh[row * DOUT + e] = hi;  g_ql[row * DOUT + e] = lo;
    } else if (p == 1) {
        g_kh[row * DOUT + e] = hi;  g_kl[row * DOUT + e] = lo;
    } else {
        const int b = row >> 12, n = row & 4095;
        g_vt[((size_t)(b * DOUT + e) << 12) + n] = hi;   // transpose scatter
    }
}

// ---------------------------------------------------------------------------
// Kernel 2: flash attention via mma.sync (split-fp16, 3-pass QK, 1-pass PV)
// ---------------------------------------------------------------------------
__device__ __forceinline__ void load_kv_tiles(char* sm, uint32_t smb, int buf,
                                              int b, int kt, int tid) {
    const __half* kh = g_kh + ((size_t)(b * SEQ + kt)) * DOUT;
    const __half* kl = g_kl + ((size_t)(b * SEQ + kt)) * DOUT;
    const __half* vt = g_vt + ((size_t)b * DOUT << 12) + kt;
#pragma unroll
    for (int i = 0; i < 4; i++) {
        const int id = tid + i * 256;           // 0..1023
        const int row = id >> 3, c = id & 7;    // K: 128 rows x 8 chunks
        cp16(smb + KH_B(buf) + row * 144 + c * 16, kh + row * DOUT + c * 8);
        cp16(smb + KL_B(buf) + row * 144 + c * 16, kl + row * DOUT + c * 8);
        const int d = id >> 4, cv = id & 15;    // V: 64 rows x 16 chunks
        cp16(smb + VT_B(buf) + d * 272 + cv * 16, vt + ((size_t)d << 12) + cv * 8);
    }
}

__global__ __launch_bounds__(256, 1)
void attn_kernel(float* __restrict__ out) {
    extern __shared__ __align__(128) char sm[];
    const uint32_t smb = smem_u32(sm);
    const int tid  = threadIdx.x;
    const int wid  = tid >> 5;
    const int lane = tid & 31;
    const int g    = lane >> 2;          // quad group: row-in-frag
    const int tq   = lane & 3;           // thread-in-quad: col-in-frag
    const int b    = blockIdx.y;
    const int q0   = blockIdx.x * BQ;
    const int r0   = wid * 16;           // this warp's 16 q-rows

    // ---- prologue: async-load Q + tiles 0,1 ----
    {
        const __half* qh = g_qh + ((size_t)(b * SEQ + q0)) * DOUT;
        const __half* ql = g_ql + ((size_t)(b * SEQ + q0)) * DOUT;
#pragma unroll
        for (int i = 0; i < 4; i++) {
            const int id = tid + i * 256;
            const int row = id >> 3, c = id & 7;
            cp16(smb + QH_B + row * 144 + c * 16, qh + row * DOUT + c * 8);
            cp16(smb + QL_B + row * 144 + c * 16, ql + row * DOUT + c * 8);
        }
        load_kv_tiles(sm, smb, 0, b, 0, tid);
        CP_COMMIT();
        load_kv_tiles(sm, smb, 1, b, BK, tid);
        CP_COMMIT();
    }

    const uint32_t* Qh2 = (const uint32_t*)(sm + QH_B);
    const uint32_t* Ql2 = (const uint32_t*)(sm + QL_B);
    uint32_t*       Pw  = (uint32_t*)(sm + P_B);

    float o[8][4];
#pragma unroll
    for (int j = 0; j < 8; j++)
#pragma unroll
        for (int k = 0; k < 4; k++) o[j][k] = 0.f;
    float m0 = -3.0e38f, m1 = -3.0e38f, l0 = 0.f, l1 = 0.f;

    for (int t = 0; t < NTILES; t++) {
        CP_WAIT1();
        __syncthreads();
        const int buf = t & 1;
        const uint32_t* Kh2 = (const uint32_t*)(sm + KH_B(buf));
        const uint32_t* Kl2 = (const uint32_t*)(sm + KL_B(buf));
        const uint32_t* Vt2 = (const uint32_t*)(sm + VT_B(buf));

        // ---- QK^T: 3-pass split-fp16, warp tile 16 x 128 ----
        float s[16][4];
#pragma unroll
        for (int j = 0; j < 16; j++)
#pragma unroll
            for (int k = 0; k < 4; k++) s[j][k] = 0.f;

#pragma unroll
        for (int ks = 0; ks < 4; ks++) {
            const int ab = (r0 + g) * 36 + ks * 8 + tq;
            const uint32_t ah0 = Qh2[ab],       ah1 = Qh2[ab + 288];
            const uint32_t ah2 = Qh2[ab + 4],   ah3 = Qh2[ab + 292];
            const uint32_t al0 = Ql2[ab],       al1 = Ql2[ab + 288];
            const uint32_t al2 = Ql2[ab + 4],   al3 = Ql2[ab + 292];
#pragma unroll
            for (int j = 0; j < 16; j++) {
                const int kb = (j * 8 + g) * 36 + ks * 8 + tq;
                const uint32_t bh0 = Kh2[kb], bh1 = Kh2[kb + 4];
                const uint32_t bl0 = Kl2[kb], bl1 = Kl2[kb + 4];
                MMA16816(s[j], ah0, ah1, ah2, ah3, bh0, bh1);
                MMA16816(s[j], ah0, ah1, ah2, ah3, bl0, bl1);
                MMA16816(s[j], al0, al1, al2, al3, bh0, bh1);
            }
        }

        // ---- online softmax (rows r0+g and r0+g+8; quad = same row) ----
        float mx0 = -3.0e38f, mx1 = -3.0e38f;
#pragma unroll
        for (int j = 0; j < 16; j++) {
            mx0 = fmaxf(mx0, fmaxf(s[j][0], s[j][1]));
            mx1 = fmaxf(mx1, fmaxf(s[j][2], s[j][3]));
        }
        mx0 = fmaxf(mx0, __shfl_xor_sync(0xffffffffu, mx0, 1));
        mx0 = fmaxf(mx0, __shfl_xor_sync(0xffffffffu, mx0, 2));
        mx1 = fmaxf(mx1, __shfl_xor_sync(0xffffffffu, mx1, 1));
        mx1 = fmaxf(mx1, __shfl_xor_sync(0xffffffffu, mx1, 2));
        const float mn0 = fmaxf(m0, mx0), mn1 = fmaxf(m1, mx1);
        const float c0 = __expf(m0 - mn0), c1 = __expf(m1 - mn1);

        float rs0 = 0.f, rs1 = 0.f;
#pragma unroll
        for (int j = 0; j < 16; j++) {
            const float e0 = __expf(s[j][0] - mn0), e1 = __expf(s[j][1] - mn0);
            const float e2 = __expf(s[j][2] - mn1), e3 = __expf(s[j][3] - mn1);
            rs0 += e0 + e1;  rs1 += e2 + e3;
            __half2 h01 = __floats2half2_rn(e0, e1);
            __half2 h23 = __floats2half2_rn(e2, e3);
            Pw[(r0 + g)     * 68 + j * 4 + tq] = *(uint32_t*)&h01;
            Pw[(r0 + g + 8) * 68 + j * 4 + tq] = *(uint32_t*)&h23;
        }
        rs0 += __shfl_xor_sync(0xffffffffu, rs0, 1);
        rs0 += __shfl_xor_sync(0xffffffffu, rs0, 2);
        rs1 += __shfl_xor_sync(0xffffffffu, rs1, 1);
        rs1 += __shfl_xor_sync(0xffffffffu, rs1, 2);
        l0 = l0 * c0 + rs0;  m0 = mn0;
        l1 = l1 * c1 + rs1;  m1 = mn1;
        __syncwarp();

        // ---- PV: rescale accumulators, then o += P @ V ----
#pragma unroll
        for (int j = 0; j < 8; j++) {
            o[j][0] *= c0; o[j][1] *= c0;
            o[j][2] *= c1; o[j][3] *= c1;
        }
        const uint32_t* Pr = (const uint32_t*)(sm + P_B);
#pragma unroll
        for (int ks = 0; ks < 8; ks++) {
            const int pb = (r0 + g) * 68 + ks * 8 + tq;
            const uint32_t a0 = Pr[pb],     a1 = Pr[pb + 544];
            const uint32_t a2 = Pr[pb + 4], a3 = Pr[pb + 548];
#pragma unroll
            for (int j = 0; j < 8; j++) {
                const int vb = (j * 8 + g) * 68 + ks * 8 + tq;
                MMA16816(o[j], a0, a1, a2, a3, Vt2[vb], Vt2[vb + 4]);
            }
        }

        __syncthreads();   // all reads of buf done before prefetch overwrites it
        if (t + 2 < NTILES)
            load_kv_tiles(sm, smb, buf, b, (t + 2) * BK, tid);
        CP_COMMIT();       // commit (possibly empty) to keep group count aligned
    }

    // ---- epilogue: normalize + store ----
    const float rl0 = __frcp_rn(l0), rl1 = __frcp_rn(l1);
    float* O = out + ((size_t)(b * SEQ + q0 + r0 + g)) * DOUT;
#pragma unroll
    for (int j = 0; j < 8; j++) {
        const int col = j * 8 + 2 * tq;
        *(float2*)&O[col]             = make_float2(o[j][0] * rl0, o[j][1] * rl0);
        *(float2*)&O[8 * DOUT + col]  = make_float2(o[j][2] * rl1, o[j][3] * rl1);
    }
}

// ---------------------------------------------------------------------------
extern "C" void kernel_launch(void* const* d_in, const int* in_sizes, int n_in,
                              void* d_out, int out_size) {
    const float* x = (const float*)d_in[0];   // [4,4096,128]
    const float* w = (const float*)d_in[1];   // [3,128,64]
    float* out = (float*)d_out;               // [4,4096,64]

    cudaFuncSetAttribute(attn_kernel,
                         cudaFuncAttributeMaxDynamicSharedMemorySize, SMEM_BYTES);

    qkv_proj_kernel<<<BATCH * SEQ, 192>>>(x, w);
    attn_kernel<<<dim3(SEQ / BQ, BATCH), 256, SMEM_BYTES>>>(out);
}

// round 5
// speedup vs baseline: 5.9833x; 1.3680x over previous
#include <cuda_runtime.h>
#include <cuda_fp16.h>
#include <cstdint>

#define BATCH 4
#define SEQ   4096
#define DIN   128
#define DOUT  64
#define BQ    128
#define BK    128
#define NTILES (SEQ / BK)

// ---- fp16 scratch — device globals, no allocation ----
__device__ __half g_qh[BATCH * SEQ * DOUT];
__device__ __half g_ql[BATCH * SEQ * DOUT];
__device__ __half g_kh[BATCH * SEQ * DOUT];
__device__ __half g_kl[BATCH * SEQ * DOUT];
__device__ __half g_vt[BATCH * DOUT * SEQ];   // transposed: [b][dout][seq]

// ---- attn smem: Q/K rows 144B (64 data + 8 pad halves), Vt rows 272B ----
#define QH_B      0
#define QL_B      18432
#define KH_B(b)   (36864  + (b) * 18432)
#define KL_B(b)   (73728  + (b) * 18432)
#define VT_B(b)   (110592 + (b) * 17408)
#define SMEM_BYTES 145408

typedef unsigned long long u64;

__device__ __forceinline__ uint32_t smem_u32(const void* p) {
    uint32_t a;
    asm("{ .reg .u64 t; cvta.to.shared.u64 t, %1; cvt.u32.u64 %0, t; }" : "=r"(a) : "l"(p));
    return a;
}
__device__ __forceinline__ void cp16(uint32_t dst, const void* src) {
    asm volatile("cp.async.cg.shared.global [%0], [%1], 16;" :: "r"(dst), "l"(src));
}
#define CP_COMMIT() asm volatile("cp.async.commit_group;" ::: "memory")
#define CP_WAIT1()  asm volatile("cp.async.wait_group 1;" ::: "memory")

#define MMA16816(c, a0, a1, a2, a3, b0, b1) \
    asm volatile("mma.sync.aligned.m16n8k16.row.col.f32.f16.f16.f32 " \
                 "{%0,%1,%2,%3}, {%4,%5,%6,%7}, {%8,%9}, {%0,%1,%2,%3};" \
                 : "+f"((c)[0]), "+f"((c)[1]), "+f"((c)[2]), "+f"((c)[3]) \
                 : "r"(a0), "r"(a1), "r"(a2), "r"(a3), "r"(b0), "r"(b1))

#define LDMX4(r0, r1, r2, r3, a) \
    asm volatile("ldmatrix.sync.aligned.m8n8.x4.shared.b16 {%0,%1,%2,%3}, [%4];" \
                 : "=r"(r0), "=r"(r1), "=r"(r2), "=r"(r3) : "r"(a))

// ---- packed f32x2 ----
__device__ __forceinline__ u64 pk2(float lo, float hi) {
    u64 r; asm("mov.b64 %0, {%1, %2};" : "=l"(r) : "f"(lo), "f"(hi)); return r;
}
__device__ __forceinline__ void fma2(u64& d, u64 a, u64 b) {
    asm("fma.rn.f32x2 %0, %1, %2, %0;" : "+l"(d) : "l"(a), "l"(b));
}
__device__ __forceinline__ void upk2(u64 v, float& lo, float& hi) {
    asm("mov.b64 {%0, %1}, %2;" : "=f"(lo), "=f"(hi) : "l"(v));
}

// ---------------------------------------------------------------------------
// Kernel 1: QKV projection, 64-token tiles, FFMA2, coalesced V^T via smem.
// ---------------------------------------------------------------------------
__global__ __launch_bounds__(256)
void qkv_proj_kernel(const float* __restrict__ x,
                     const float* __restrict__ w) {
    __shared__ float  xs[64][129];          // [token][d], bcast-friendly
    __shared__ __half vts[64][72];          // [e][token], staged V^T

    const int b  = blockIdx.y;
    const int n0 = blockIdx.x * 64;
    const int tid = threadIdx.x;

    // load x tile [64][128] coalesced
    const float* xg = x + ((size_t)(b * SEQ + n0)) * DIN;
#pragma unroll
    for (int i = 0; i < 8; i++) {
        const int id4 = tid + i * 256;          // 2048 float4s
        const int row = id4 >> 5, c4 = (id4 & 31) << 2;
        const float4 v = *(const float4*)&xg[row * DIN + c4];
        xs[row][c4] = v.x; xs[row][c4 + 1] = v.y;
        xs[row][c4 + 2] = v.z; xs[row][c4 + 3] = v.w;
    }
    __syncthreads();

    const int tx = tid & 31, ty = tid >> 5;
    const int tok0 = ty * 8;

    u64 acc2[4][6];
#pragma unroll
    for (int t = 0; t < 4; t++)
#pragma unroll
        for (int c = 0; c < 6; c++) acc2[t][c] = 0ull;

#pragma unroll 2
    for (int d = 0; d < DIN; d++) {
        u64 xp[4];
#pragma unroll
        for (int t = 0; t < 4; t++)
            xp[t] = pk2(xs[tok0 + 2 * t][d], xs[tok0 + 2 * t + 1][d]);
#pragma unroll
        for (int c = 0; c < 6; c++) {
            const int p = c >> 1, e = tx + ((c & 1) << 5);
            const float wv = __ldg(&w[(p * DIN + d) * DOUT + e]);
            const u64 w2 = pk2(wv, wv);
#pragma unroll
            for (int t = 0; t < 4; t++) fma2(acc2[t][c], xp[t], w2);
        }
    }

    // write Q/K hi+lo (coalesced 2B x 32 lanes = 64B) and stage V
#pragma unroll
    for (int t = 0; t < 4; t++) {
#pragma unroll
        for (int c = 0; c < 6; c++) {
            float v0, v1; upk2(acc2[t][c], v0, v1);
            const int e = tx + ((c & 1) << 5);
            const size_t r0 = (size_t)(b * SEQ + n0 + tok0 + 2 * t) * DOUT + e;
            const size_t r1 = r0 + DOUT;
            if (c < 2) {
                v0 *= 0.125f; v1 *= 0.125f;
                const __half h0 = __float2half_rn(v0), h1 = __float2half_rn(v1);
                g_qh[r0] = h0; g_ql[r0] = __float2half_rn(v0 - __half2float(h0));
                g_qh[r1] = h1; g_ql[r1] = __float2half_rn(v1 - __half2float(h1));
            } else if (c < 4) {
                const __half h0 = __float2half_rn(v0), h1 = __float2half_rn(v1);
                g_kh[r0] = h0; g_kl[r0] = __float2half_rn(v0 - __half2float(h0));
                g_kh[r1] = h1; g_kl[r1] = __float2half_rn(v1 - __half2float(h1));
            } else {
                vts[e][tok0 + 2 * t]     = __float2half_rn(v0);
                vts[e][tok0 + 2 * t + 1] = __float2half_rn(v1);
            }
        }
    }
    __syncthreads();

    // write V^T coalesced: row e -> 64 consecutive tokens (128B)
    const int e = tid >> 2, seg = tid & 3;
    const uint4* srcv = (const uint4*)&vts[e][seg * 16];
    uint4* dstv = (uint4*)&g_vt[(((size_t)(b * DOUT + e)) << 12) + n0 + seg * 16];
    dstv[0] = srcv[0];
    dstv[1] = srcv[1];
}

// ---------------------------------------------------------------------------
// Kernel 2: flash attention via mma.sync + ldmatrix; P passes through regs.
// ---------------------------------------------------------------------------
__device__ __forceinline__ void load_kv_tiles(uint32_t smb, int buf,
                                              int b, int kt, int tid) {
    const __half* kh = g_kh + ((size_t)(b * SEQ + kt)) * DOUT;
    const __half* kl = g_kl + ((size_t)(b * SEQ + kt)) * DOUT;
    const __half* vt = g_vt + (((size_t)b * DOUT) << 12) + kt;
#pragma unroll
    for (int i = 0; i < 4; i++) {
        const int id = tid + i * 256;
        const int row = id >> 3, c = id & 7;
        cp16(smb + KH_B(buf) + row * 144 + c * 16, kh + row * DOUT + c * 8);
        cp16(smb + KL_B(buf) + row * 144 + c * 16, kl + row * DOUT + c * 8);
        const int d = id >> 4, cv = id & 15;
        cp16(smb + VT_B(buf) + d * 272 + cv * 16, vt + ((size_t)d << 12) + cv * 8);
    }
}

__global__ __launch_bounds__(256, 1)
void attn_kernel(float* __restrict__ out) {
    extern __shared__ __align__(128) char sm[];
    const uint32_t smb = smem_u32(sm);
    const int tid  = threadIdx.x;
    const int wid  = tid >> 5;
    const int lane = tid & 31;
    const int g    = lane >> 2;
    const int tq   = lane & 3;
    const int b    = blockIdx.y;
    const int q0   = blockIdx.x * BQ;
    const int r0   = wid * 16;

    // ldmatrix lane-address components
    const int lt = lane >> 3, lr = lane & 7;
    // A tiles: t0(r+0..7,k0-7) t1(r+8..15,k0-7) t2(r+0..7,k8-15) t3(r+8..15,k8-15)
    const uint32_t aoff = (uint32_t)((r0 + ((lt & 1) << 3) + lr) * 144 + ((lt >> 1) << 4));
    // B tiles (K/V): t0(n+0..7,klo) t1(n+0..7,khi) t2(n+8..15,klo) t3(n+8..15,khi)
    const uint32_t kboff = (uint32_t)(((((lane >> 4) << 3) + lr)) * 144 + ((lt & 1) << 4));
    const uint32_t vboff = (uint32_t)(((((lane >> 4) << 3) + lr)) * 272 + ((lt & 1) << 4));

    // ---- prologue ----
    {
        const __half* qh = g_qh + ((size_t)(b * SEQ + q0)) * DOUT;
        const __half* ql = g_ql + ((size_t)(b * SEQ + q0)) * DOUT;
#pragma unroll
        for (int i = 0; i < 4; i++) {
            const int id = tid + i * 256;
            const int row = id >> 3, c = id & 7;
            cp16(smb + QH_B + row * 144 + c * 16, qh + row * DOUT + c * 8);
            cp16(smb + QL_B + row * 144 + c * 16, ql + row * DOUT + c * 8);
        }
        load_kv_tiles(smb, 0, b, 0, tid);
        CP_COMMIT();
        load_kv_tiles(smb, 1, b, BK, tid);
        CP_COMMIT();
    }

    float o[8][4];
#pragma unroll
    for (int j = 0; j < 8; j++)
#pragma unroll
        for (int k = 0; k < 4; k++) o[j][k] = 0.f;
    float m0 = -3.0e38f, m1 = -3.0e38f, l0 = 0.f, l1 = 0.f;

    for (int t = 0; t < NTILES; t++) {
        CP_WAIT1();
        __syncthreads();
        const int buf = t & 1;
        const uint32_t khb = smb + KH_B(buf) + kboff;
        const uint32_t klb = smb + KL_B(buf) + kboff;
        const uint32_t vtb = smb + VT_B(buf) + vboff;

        // ---- QK^T: 3-pass split-fp16, ldmatrix fragments ----
        float s[16][4];
#pragma unroll
        for (int j = 0; j < 16; j++)
#pragma unroll
            for (int k = 0; k < 4; k++) s[j][k] = 0.f;

#pragma unroll
        for (int ks = 0; ks < 4; ks++) {
            uint32_t ah0, ah1, ah2, ah3, al0, al1, al2, al3;
            LDMX4(ah0, ah1, ah2, ah3, smb + QH_B + aoff + ks * 32);
            LDMX4(al0, al1, al2, al3, smb + QL_B + aoff + ks * 32);
#pragma unroll
            for (int jp = 0; jp < 8; jp++) {
                uint32_t bh0, bh1, bh2, bh3, bl0, bl1, bl2, bl3;
                LDMX4(bh0, bh1, bh2, bh3, khb + jp * (16 * 144) + ks * 32);
                LDMX4(bl0, bl1, bl2, bl3, klb + jp * (16 * 144) + ks * 32);
                MMA16816(s[2 * jp],     ah0, ah1, ah2, ah3, bh0, bh1);
                MMA16816(s[2 * jp],     ah0, ah1, ah2, ah3, bl0, bl1);
                MMA16816(s[2 * jp],     al0, al1, al2, al3, bh0, bh1);
                MMA16816(s[2 * jp + 1], ah0, ah1, ah2, ah3, bh2, bh3);
                MMA16816(s[2 * jp + 1], ah0, ah1, ah2, ah3, bl2, bl3);
                MMA16816(s[2 * jp + 1], al0, al1, al2, al3, bh2, bh3);
            }
        }

        // ---- online softmax; pack P directly into PV A-fragments ----
        float mx0 = -3.0e38f, mx1 = -3.0e38f;
#pragma unroll
        for (int j = 0; j < 16; j++) {
            mx0 = fmaxf(mx0, fmaxf(s[j][0], s[j][1]));
            mx1 = fmaxf(mx1, fmaxf(s[j][2], s[j][3]));
        }
        mx0 = fmaxf(mx0, __shfl_xor_sync(0xffffffffu, mx0, 1));
        mx0 = fmaxf(mx0, __shfl_xor_sync(0xffffffffu, mx0, 2));
        mx1 = fmaxf(mx1, __shfl_xor_sync(0xffffffffu, mx1, 1));
        mx1 = fmaxf(mx1, __shfl_xor_sync(0xffffffffu, mx1, 2));
        const float mn0 = fmaxf(m0, mx0), mn1 = fmaxf(m1, mx1);
        const float c0 = __expf(m0 - mn0), c1 = __expf(m1 - mn1);

        uint32_t pa[8][4];
        float rs0 = 0.f, rs1 = 0.f;
#pragma unroll
        for (int j = 0; j < 16; j++) {
            const float e0 = __expf(s[j][0] - mn0), e1 = __expf(s[j][1] - mn0);
            const float e2 = __expf(s[j][2] - mn1), e3 = __expf(s[j][3] - mn1);
            rs0 += e0 + e1;  rs1 += e2 + e3;
            const __half2 h01 = __floats2half2_rn(e0, e1);
            const __half2 h23 = __floats2half2_rn(e2, e3);
            pa[j >> 1][(j & 1) * 2 + 0] = *(const uint32_t*)&h01;
            pa[j >> 1][(j & 1) * 2 + 1] = *(const uint32_t*)&h23;
        }
        rs0 += __shfl_xor_sync(0xffffffffu, rs0, 1);
        rs0 += __shfl_xor_sync(0xffffffffu, rs0, 2);
        rs1 += __shfl_xor_sync(0xffffffffu, rs1, 1);
        rs1 += __shfl_xor_sync(0xffffffffu, rs1, 2);
        l0 = l0 * c0 + rs0;  m0 = mn0;
        l1 = l1 * c1 + rs1;  m1 = mn1;

        // ---- PV: rescale then o += P @ V (A from regs, B via ldmatrix) ----
#pragma unroll
        for (int j = 0; j < 8; j++) {
            o[j][0] *= c0; o[j][1] *= c0;
            o[j][2] *= c1; o[j][3] *= c1;
        }
#pragma unroll
        for (int ks = 0; ks < 8; ks++) {
#pragma unroll
            for (int jp = 0; jp < 4; jp++) {
                uint32_t v0, v1, v2, v3;
                LDMX4(v0, v1, v2, v3, vtb + jp * (16 * 272) + ks * 32);
                MMA16816(o[2 * jp],     pa[ks][0], pa[ks][1], pa[ks][2], pa[ks][3], v0, v1);
                MMA16816(o[2 * jp + 1], pa[ks][0], pa[ks][1], pa[ks][2], pa[ks][3], v2, v3);
            }
        }

        __syncthreads();
        if (t + 2 < NTILES)
            load_kv_tiles(smb, buf, b, (t + 2) * BK, tid);
        CP_COMMIT();
    }

    // ---- epilogue ----
    const float rl0 = __frcp_rn(l0), rl1 = __frcp_rn(l1);
    float* O = out + ((size_t)(b * SEQ + q0 + r0 + g)) * DOUT;
#pragma unroll
    for (int j = 0; j < 8; j++) {
        const int col = j * 8 + 2 * tq;
        *(float2*)&O[col]            = make_float2(o[j][0] * rl0, o[j][1] * rl0);
        *(float2*)&O[8 * DOUT + col] = make_float2(o[j][2] * rl1, o[j][3] * rl1);
    }
}

// ---------------------------------------------------------------------------
extern "C" void kernel_launch(void* const* d_in, const int* in_sizes, int n_in,
                              void* d_out, int out_size) {
    const float* x = (const float*)d_in[0];   // [4,4096,128]
    const float* w = (const float*)d_in[1];   // [3,128,64]
    float* out = (float*)d_out;               // [4,4096,64]

    cudaFuncSetAttribute(attn_kernel,
                         cudaFuncAttributeMaxDynamicSharedMemorySize, SMEM_BYTES);

    qkv_proj_kernel<<<dim3(SEQ / 64, BATCH), 256>>>(x, w);
    attn_kernel<<<dim3(SEQ / BQ, BATCH), 256, SMEM_BYTES>>>(out);
}

// round 6
// speedup vs baseline: 6.3462x; 1.0606x over previous
#include <cuda_runtime.h>
#include <cuda_fp16.h>
#include <cstdint>

#define BATCH 4
#define SEQ   4096
#define DIN   128
#define DOUT  64
#define BQ    128
#define BK    128
#define NTILES (SEQ / BK)

// Q pre-scale: 1/sqrt(64) * log2(e)  (softmax runs in exp2 domain)
#define QSCALE 0.1803368801111244f

// ---- fp16 scratch — device globals, no allocation ----
__device__ __half g_qh[BATCH * SEQ * DOUT];
__device__ __half g_ql[BATCH * SEQ * DOUT];
__device__ __half g_kh[BATCH * SEQ * DOUT];
__device__ __half g_kl[BATCH * SEQ * DOUT];
__device__ __half g_vt[BATCH * DOUT * SEQ];   // transposed: [b][dout][seq]

// ---- attn smem: 3-stage KV pipeline ----
#define QH_B      0
#define QL_B      18432
#define ST_B(s)   (36864 + (s) * 54272)
#define KH_B(s)   (ST_B(s))
#define KL_B(s)   (ST_B(s) + 18432)
#define VT_B(s)   (ST_B(s) + 36864)
#define SMEM_BYTES 199680

typedef unsigned long long u64;

__device__ __forceinline__ uint32_t smem_u32(const void* p) {
    uint32_t a;
    asm("{ .reg .u64 t; cvta.to.shared.u64 t, %1; cvt.u32.u64 %0, t; }" : "=r"(a) : "l"(p));
    return a;
}
__device__ __forceinline__ void cp16(uint32_t dst, const void* src) {
    asm volatile("cp.async.cg.shared.global [%0], [%1], 16;" :: "r"(dst), "l"(src));
}
#define CP_COMMIT() asm volatile("cp.async.commit_group;" ::: "memory")
#define CP_WAIT1()  asm volatile("cp.async.wait_group 1;" ::: "memory")

__device__ __forceinline__ float ex2f(float x) {
    float r; asm("ex2.approx.ftz.f32 %0, %1;" : "=f"(r) : "f"(x)); return r;
}

#define MMA16816(c, a0, a1, a2, a3, b0, b1) \
    asm volatile("mma.sync.aligned.m16n8k16.row.col.f32.f16.f16.f32 " \
                 "{%0,%1,%2,%3}, {%4,%5,%6,%7}, {%8,%9}, {%0,%1,%2,%3};" \
                 : "+f"((c)[0]), "+f"((c)[1]), "+f"((c)[2]), "+f"((c)[3]) \
                 : "r"(a0), "r"(a1), "r"(a2), "r"(a3), "r"(b0), "r"(b1))

#define LDMX4(r0, r1, r2, r3, a) \
    asm volatile("ldmatrix.sync.aligned.m8n8.x4.shared.b16 {%0,%1,%2,%3}, [%4];" \
                 : "=r"(r0), "=r"(r1), "=r"(r2), "=r"(r3) : "r"(a))

// ---- packed f32x2 ----
__device__ __forceinline__ u64 pk2(float lo, float hi) {
    u64 r; asm("mov.b64 %0, {%1, %2};" : "=l"(r) : "f"(lo), "f"(hi)); return r;
}
__device__ __forceinline__ void fma2(u64& d, u64 a, u64 b) {
    asm("fma.rn.f32x2 %0, %1, %2, %0;" : "+l"(d) : "l"(a), "l"(b));
}
__device__ __forceinline__ void upk2(u64 v, float& lo, float& hi) {
    asm("mov.b64 {%0, %1}, %2;" : "=f"(lo), "=f"(hi) : "l"(v));
}

// ---------------------------------------------------------------------------
// Kernel 1: QKV projection. 128-token tiles, 16 tokens/thread,
// packed-column (e, e+32) f32x2 accumulators, coalesced V^T via smem staging.
// ---------------------------------------------------------------------------
#define XS_PAD 132                       // floats per x row (128 + 4)
#define VTS_PAD 132                      // halves per vts row
#define QKV_XS_B  0                      // 128 * 132 * 4 = 67584
#define QKV_VT_B  67584                  // 64 * 132 * 2 = 16896
#define QKV_SMEM  84480

__global__ __launch_bounds__(256)
void qkv_proj_kernel(const float* __restrict__ x,
                     const float* __restrict__ w) {
    extern __shared__ __align__(16) char qsm[];
    float*  xs  = (float*)(qsm + QKV_XS_B);     // [token][d] padded
    __half* vts = (__half*)(qsm + QKV_VT_B);    // [e][token] padded

    const int b   = blockIdx.y;
    const int n0  = blockIdx.x * 128;
    const int tid = threadIdx.x;

    // load x tile [128][128], coalesced float4
    const float* xg = x + ((size_t)(b * SEQ + n0)) * DIN;
#pragma unroll
    for (int i = 0; i < 16; i++) {
        const int id4 = tid + i * 256;
        const int tok = id4 >> 5, c4 = (id4 & 31) << 2;
        *(float4*)&xs[tok * XS_PAD + c4] = *(const float4*)&xg[tok * DIN + c4];
    }
    __syncthreads();

    const int tx = tid & 31, ty = tid >> 5;
    const int tok0 = ty * 16;

    u64 acc[16][3];
#pragma unroll
    for (int t = 0; t < 16; t++)
#pragma unroll
        for (int p = 0; p < 3; p++) acc[t][p] = 0ull;

#pragma unroll 2
    for (int d = 0; d < DIN; d++) {
        const u64 wq = pk2(__ldg(&w[(0 * DIN + d) * DOUT + tx]),
                           __ldg(&w[(0 * DIN + d) * DOUT + tx + 32]));
        const u64 wk = pk2(__ldg(&w[(1 * DIN + d) * DOUT + tx]),
                           __ldg(&w[(1 * DIN + d) * DOUT + tx + 32]));
        const u64 wv = pk2(__ldg(&w[(2 * DIN + d) * DOUT + tx]),
                           __ldg(&w[(2 * DIN + d) * DOUT + tx + 32]));
#pragma unroll
        for (int t = 0; t < 16; t++) {
            const float xv = xs[(tok0 + t) * XS_PAD + d];   // broadcast LDS
            const u64 x2 = pk2(xv, xv);
            fma2(acc[t][0], x2, wq);
            fma2(acc[t][1], x2, wk);
            fma2(acc[t][2], x2, wv);
        }
    }

    // store Q/K hi+lo (coalesced) and stage V in smem
#pragma unroll
    for (int t = 0; t < 16; t++) {
        const size_t row = (size_t)(b * SEQ + n0 + tok0 + t) * DOUT;
        float v0, v1;
        upk2(acc[t][0], v0, v1);
        v0 *= QSCALE; v1 *= QSCALE;
        __half h0 = __float2half_rn(v0), h1 = __float2half_rn(v1);
        g_qh[row + tx]      = h0; g_ql[row + tx]      = __float2half_rn(v0 - __half2float(h0));
        g_qh[row + tx + 32] = h1; g_ql[row + tx + 32] = __float2half_rn(v1 - __half2float(h1));
        upk2(acc[t][1], v0, v1);
        h0 = __float2half_rn(v0); h1 = __float2half_rn(v1);
        g_kh[row + tx]      = h0; g_kl[row + tx]      = __float2half_rn(v0 - __half2float(h0));
        g_kh[row + tx + 32] = h1; g_kl[row + tx + 32] = __float2half_rn(v1 - __half2float(h1));
        upk2(acc[t][2], v0, v1);
        vts[tx * VTS_PAD + tok0 + t]        = __float2half_rn(v0);
        vts[(tx + 32) * VTS_PAD + tok0 + t] = __float2half_rn(v1);
    }
    __syncthreads();

    // write V^T coalesced: row e -> 32 consecutive tokens (64B) per thread
    const int e = tid >> 2, seg = tid & 3;
    const u64* srcv = (const u64*)(vts + e * VTS_PAD + seg * 32);
    uint4* dstv = (uint4*)&g_vt[(((size_t)(b * DOUT + e)) << 12) + n0 + seg * 32];
    u64 r[8];
#pragma unroll
    for (int k = 0; k < 8; k++) r[k] = srcv[k];
#pragma unroll
    for (int k = 0; k < 4; k++)
        dstv[k] = make_uint4((uint32_t)r[2*k], (uint32_t)(r[2*k] >> 32),
                             (uint32_t)r[2*k+1], (uint32_t)(r[2*k+1] >> 32));
}

// ---------------------------------------------------------------------------
// Kernel 2: flash attention via mma.sync + pipelined ldmatrix, 3-stage cp.async.
// ---------------------------------------------------------------------------
__device__ __forceinline__ void load_kv_tiles(uint32_t smb, int stg,
                                              int b, int kt, int tid) {
    const __half* kh = g_kh + ((size_t)(b * SEQ + kt)) * DOUT;
    const __half* kl = g_kl + ((size_t)(b * SEQ + kt)) * DOUT;
    const __half* vt = g_vt + (((size_t)b * DOUT) << 12) + kt;
#pragma unroll
    for (int i = 0; i < 4; i++) {
        const int id = tid + i * 256;
        const int row = id >> 3, c = id & 7;
        cp16(smb + KH_B(stg) + row * 144 + c * 16, kh + row * DOUT + c * 8);
        cp16(smb + KL_B(stg) + row * 144 + c * 16, kl + row * DOUT + c * 8);
        const int d = id >> 4, cv = id & 15;
        cp16(smb + VT_B(stg) + d * 272 + cv * 16, vt + ((size_t)d << 12) + cv * 8);
    }
}

__global__ __launch_bounds__(256, 1)
void attn_kernel(float* __restrict__ out) {
    extern __shared__ __align__(128) char sm[];
    const uint32_t smb = smem_u32(sm);
    const int tid  = threadIdx.x;
    const int wid  = tid >> 5;
    const int lane = tid & 31;
    const int g    = lane >> 2;
    const int tq   = lane & 3;
    const int b    = blockIdx.y;
    const int q0   = blockIdx.x * BQ;
    const int r0   = wid * 16;

    const int lt = lane >> 3, lr = lane & 7;
    const uint32_t aoff  = (uint32_t)((r0 + ((lt & 1) << 3) + lr) * 144 + ((lt >> 1) << 4));
    const uint32_t kboff = (uint32_t)((((lane >> 4) << 3) + lr) * 144 + ((lt & 1) << 4));
    const uint32_t vboff = (uint32_t)((((lane >> 4) << 3) + lr) * 272 + ((lt & 1) << 4));

    // ---- prologue: Q + stages 0,1 ----
    {
        const __half* qh = g_qh + ((size_t)(b * SEQ + q0)) * DOUT;
        const __half* ql = g_ql + ((size_t)(b * SEQ + q0)) * DOUT;
#pragma unroll
        for (int i = 0; i < 4; i++) {
            const int id = tid + i * 256;
            const int row = id >> 3, c = id & 7;
            cp16(smb + QH_B + row * 144 + c * 16, qh + row * DOUT + c * 8);
            cp16(smb + QL_B + row * 144 + c * 16, ql + row * DOUT + c * 8);
        }
        load_kv_tiles(smb, 0, b, 0, tid);
        CP_COMMIT();
        load_kv_tiles(smb, 1, b, BK, tid);
        CP_COMMIT();
    }

    float o[8][4];
#pragma unroll
    for (int j = 0; j < 8; j++)
#pragma unroll
        for (int k = 0; k < 4; k++) o[j][k] = 0.f;
    float m0 = -3.0e38f, m1 = -3.0e38f, l0 = 0.f, l1 = 0.f;

    for (int t = 0; t < NTILES; t++) {
        CP_WAIT1();           // stage t's data landed (stage t+1 may pend)
        __syncthreads();      // visibility + all warps done reading stage (t+2)%3
        if (t + 2 < NTILES)
            load_kv_tiles(smb, (t + 2) % 3, b, (t + 2) * BK, tid);
        CP_COMMIT();

        const int stg = t % 3;
        const uint32_t khb = smb + KH_B(stg) + kboff;
        const uint32_t klb = smb + KL_B(stg) + kboff;
        const uint32_t vtb = smb + VT_B(stg) + vboff;

        // ---- QK^T: 3-pass split-fp16, double-buffered B fragments ----
        float s[16][4];
#pragma unroll
        for (int j = 0; j < 16; j++)
#pragma unroll
            for (int k = 0; k < 4; k++) s[j][k] = 0.f;

        uint32_t bh[2][4], bl[2][4];
        LDMX4(bh[0][0], bh[0][1], bh[0][2], bh[0][3], khb);
        LDMX4(bl[0][0], bl[0][1], bl[0][2], bl[0][3], klb);
#pragma unroll
        for (int ks = 0; ks < 4; ks++) {
            uint32_t ah0, ah1, ah2, ah3, al0, al1, al2, al3;
            LDMX4(ah0, ah1, ah2, ah3, smb + QH_B + aoff + ks * 32);
            LDMX4(al0, al1, al2, al3, smb + QL_B + aoff + ks * 32);
#pragma unroll
            for (int jp = 0; jp < 8; jp++) {
                const int cur = (ks * 8 + jp) & 1, nxt = cur ^ 1;
                if (!(ks == 3 && jp == 7)) {
                    const uint32_t nk = (jp < 7) ? (khb + ks * 32 + (jp + 1) * 2304)
                                                 : (khb + (ks + 1) * 32);
                    const uint32_t nl = (jp < 7) ? (klb + ks * 32 + (jp + 1) * 2304)
                                                 : (klb + (ks + 1) * 32);
                    LDMX4(bh[nxt][0], bh[nxt][1], bh[nxt][2], bh[nxt][3], nk);
                    LDMX4(bl[nxt][0], bl[nxt][1], bl[nxt][2], bl[nxt][3], nl);
                }
                MMA16816(s[2*jp],   ah0, ah1, ah2, ah3, bh[cur][0], bh[cur][1]);
                MMA16816(s[2*jp],   ah0, ah1, ah2, ah3, bl[cur][0], bl[cur][1]);
                MMA16816(s[2*jp],   al0, al1, al2, al3, bh[cur][0], bh[cur][1]);
                MMA16816(s[2*jp+1], ah0, ah1, ah2, ah3, bh[cur][2], bh[cur][3]);
                MMA16816(s[2*jp+1], ah0, ah1, ah2, ah3, bl[cur][2], bl[cur][3]);
                MMA16816(s[2*jp+1], al0, al1, al2, al3, bh[cur][2], bh[cur][3]);
            }
        }

        // ---- online softmax in exp2 domain; P packed into PV A-fragments ----
        float mx0 = -3.0e38f, mx1 = -3.0e38f;
#pragma unroll
        for (int j = 0; j < 16; j++) {
            mx0 = fmaxf(mx0, fmaxf(s[j][0], s[j][1]));
            mx1 = fmaxf(mx1, fmaxf(s[j][2], s[j][3]));
        }
        mx0 = fmaxf(mx0, __shfl_xor_sync(0xffffffffu, mx0, 1));
        mx0 = fmaxf(mx0, __shfl_xor_sync(0xffffffffu, mx0, 2));
        mx1 = fmaxf(mx1, __shfl_xor_sync(0xffffffffu, mx1, 1));
        mx1 = fmaxf(mx1, __shfl_xor_sync(0xffffffffu, mx1, 2));
        const float mn0 = fmaxf(m0, mx0), mn1 = fmaxf(m1, mx1);
        const float c0 = ex2f(m0 - mn0), c1 = ex2f(m1 - mn1);

        uint32_t pa[8][4];
        float rs0 = 0.f, rs1 = 0.f;
#pragma unroll
        for (int j = 0; j < 16; j++) {
            const float e0 = ex2f(s[j][0] - mn0), e1 = ex2f(s[j][1] - mn0);
            const float e2 = ex2f(s[j][2] - mn1), e3 = ex2f(s[j][3] - mn1);
            rs0 += e0 + e1;  rs1 += e2 + e3;
            const __half2 h01 = __floats2half2_rn(e0, e1);
            const __half2 h23 = __floats2half2_rn(e2, e3);
            pa[j >> 1][(j & 1) * 2 + 0] = *(const uint32_t*)&h01;
            pa[j >> 1][(j & 1) * 2 + 1] = *(const uint32_t*)&h23;
        }
        rs0 += __shfl_xor_sync(0xffffffffu, rs0, 1);
        rs0 += __shfl_xor_sync(0xffffffffu, rs0, 2);
        rs1 += __shfl_xor_sync(0xffffffffu, rs1, 1);
        rs1 += __shfl_xor_sync(0xffffffffu, rs1, 2);
        l0 = l0 * c0 + rs0;  m0 = mn0;
        l1 = l1 * c1 + rs1;  m1 = mn1;

        // ---- PV: rescale then o += P @ V, double-buffered V fragments ----
#pragma unroll
        for (int j = 0; j < 8; j++) {
            o[j][0] *= c0; o[j][1] *= c0;
            o[j][2] *= c1; o[j][3] *= c1;
        }
        uint32_t vb[2][4];
        LDMX4(vb[0][0], vb[0][1], vb[0][2], vb[0][3], vtb);
#pragma unroll
        for (int ks = 0; ks < 8; ks++) {
#pragma unroll
            for (int jp = 0; jp < 4; jp++) {
                const int cur = (ks * 4 + jp) & 1, nxt = cur ^ 1;
                if (!(ks == 7 && jp == 3)) {
                    const uint32_t nv = (jp < 3) ? (vtb + ks * 32 + (jp + 1) * 4352)
                                                 : (vtb + (ks + 1) * 32);
                    LDMX4(vb[nxt][0], vb[nxt][1], vb[nxt][2], vb[nxt][3], nv);
                }
                MMA16816(o[2*jp],   pa[ks][0], pa[ks][1], pa[ks][2], pa[ks][3],
                         vb[cur][0], vb[cur][1]);
                MMA16816(o[2*jp+1], pa[ks][0], pa[ks][1], pa[ks][2], pa[ks][3],
                         vb[cur][2], vb[cur][3]);
            }
        }
    }

    // ---- epilogue ----
    const float rl0 = __frcp_rn(l0), rl1 = __frcp_rn(l1);
    float* O = out + ((size_t)(b * SEQ + q0 + r0 + g)) * DOUT;
#pragma unroll
    for (int j = 0; j < 8; j++) {
        const int col = j * 8 + 2 * tq;
        *(float2*)&O[col]            = make_float2(o[j][0] * rl0, o[j][1] * rl0);
        *(float2*)&O[8 * DOUT + col] = make_float2(o[j][2] * rl1, o[j][3] * rl1);
    }
}

// ---------------------------------------------------------------------------
extern "C" void kernel_launch(void* const* d_in, const int* in_sizes, int n_in,
                              void* d_out, int out_size) {
    const float* x = (const float*)d_in[0];   // [4,4096,128]
    const float* w = (const float*)d_in[1];   // [3,128,64]
    float* out = (float*)d_out;               // [4,4096,64]

    cudaFuncSetAttribute(attn_kernel,
                         cudaFuncAttributeMaxDynamicSharedMemorySize, SMEM_BYTES);
    cudaFuncSetAttribute(qkv_proj_kernel,
                         cudaFuncAttributeMaxDynamicSharedMemorySize, QKV_SMEM);

    qkv_proj_kernel<<<dim3(SEQ / 128, BATCH), 256, QKV_SMEM>>>(x, w);
    attn_kernel<<<dim3(SEQ / BQ, BATCH), 256, SMEM_BYTES>>>(out);
}